// round 5
// baseline (speedup 1.0000x reference)
#include <cuda_runtime.h>

// Problem constants (fixed shapes from reference)
#define Bn  4
#define Cn  128
#define Hn  64
#define Wn  64
#define Ln  16
#define Kn  64
#define CDn 8

typedef unsigned long long u64;

// ---- packed f32x2 helpers (sm_100+ PTX; ptxas won't auto-fuse these) ----
__device__ __forceinline__ u64 pack2(float x, float y) {
    u64 r; asm("mov.b64 %0, {%1, %2};" : "=l"(r) : "f"(x), "f"(y)); return r;
}
__device__ __forceinline__ void unpack2(u64 v, float& x, float& y) {
    asm("mov.b64 {%0, %1}, %2;" : "=f"(x), "=f"(y) : "l"(v));
}
__device__ __forceinline__ u64 add2(u64 a, u64 b) {
    u64 d; asm("add.rn.f32x2 %0, %1, %2;" : "=l"(d) : "l"(a), "l"(b)); return d;
}
__device__ __forceinline__ u64 fma2(u64 a, u64 b, u64 c) {
    u64 d; asm("fma.rn.f32x2 %0, %1, %2, %3;" : "=l"(d) : "l"(a), "l"(b), "l"(c)); return d;
}
__device__ __forceinline__ u64 mul2(u64 a, u64 b) {
    u64 d; asm("mul.rn.f32x2 %0, %1, %2;" : "=l"(d) : "l"(a), "l"(b)); return d;
}

// One thread: one (b, h, w, l) slot. Block (64, 2) = 128 threads; lanes sweep
// w (coalesced z/q traffic); each warp has a single l -> all code smem reads
// are broadcasts. 2048 blocks (~14/SM, single wave) for fine-grain tail.
// __launch_bounds__(128, 10) caps regs ~51 so 10 blocks (40 warps) reside
// per SM -> ~1.4x more eligible warps than round 4.
//
// Argmin: two independent trackers (k in [0,32) and [32,64)).
//   best = fminf(best, dist)           -> FMNMX, 4-cyc loop chain
//   bi   = (dist < best_old) ? k : bi  -> SEL hangs off the chain
// Identical semantics to sequential strict-< argmin (first k wins ties).
__global__ __launch_bounds__(128, 10) void vq_kernel(
    const float* __restrict__ z,      // (B, C, H, W)
    const float* __restrict__ codes,  // (L, K, CD)
    float* __restrict__ qout,         // (B, C, H, W) or null
    float* __restrict__ idxf,         // (B, H, W, L) as float or null
    int*   __restrict__ idxi)         // (B, H, W, L) as int or null
{
    // Negated codes for this block's 2 l-slots: (z + (-c)) == (z - c) exactly.
    __shared__ __align__(16) float cneg[2 * Kn * CDn];  // 4 KB

    const int tid = threadIdx.y * 64 + threadIdx.x;
    const int l0  = blockIdx.x * 2;

    #pragma unroll
    for (int i = tid; i < 2 * Kn * CDn / 4; i += 128) {
        const float4 v = reinterpret_cast<const float4*>(codes + l0 * Kn * CDn)[i];
        reinterpret_cast<float4*>(cneg)[i] = make_float4(-v.x, -v.y, -v.z, -v.w);
    }
    __syncthreads();

    const int w  = threadIdx.x;
    const int ls = threadIdx.y;
    const int l  = l0 + ls;
    const int h  = blockIdx.y;
    const int b  = blockIdx.z;

    // Load z for this pixel: 8 channels (channel stride = H*W, coalesced over w)
    const float* zb = z + ((b * Cn + l * CDn) * Hn + h) * Wn + w;
    u64 zp[4];
    #pragma unroll
    for (int i = 0; i < 4; i++) {
        const float e0 = zb[(2 * i)     * Hn * Wn];
        const float e1 = zb[(2 * i + 1) * Hn * Wn];
        zp[i] = pack2(e0, e1);
    }

    // Codes for this l as float4 pairs: code k -> cb[2k], cb[2k+1]
    const float4* __restrict__ cb =
        reinterpret_cast<const float4*>(cneg + ls * Kn * CDn);

    float best0 = 3.4e38f, best1 = 3.4e38f;
    int   bi0 = 0, bi1 = 32;

    #pragma unroll
    for (int kk = 0; kk < 32; kk++) {
        // ---- tracker 0: k = kk ----
        {
            const float4 a = cb[2 * kk];
            const float4 c = cb[2 * kk + 1];
            u64 d, s;
            s = add2(zp[0], pack2(a.x, a.y)); d = mul2(s, s);
            s = add2(zp[1], pack2(a.z, a.w)); d = fma2(s, s, d);
            s = add2(zp[2], pack2(c.x, c.y)); d = fma2(s, s, d);
            s = add2(zp[3], pack2(c.z, c.w)); d = fma2(s, s, d);
            float dx, dy; unpack2(d, dx, dy);
            const float dist = dx + dy;
            const float bo = best0;
            best0 = fminf(bo, dist);
            bi0   = (dist < bo) ? kk : bi0;
        }
        // ---- tracker 1: k = kk + 32 ----
        {
            const float4 a = cb[2 * (kk + 32)];
            const float4 c = cb[2 * (kk + 32) + 1];
            u64 d, s;
            s = add2(zp[0], pack2(a.x, a.y)); d = mul2(s, s);
            s = add2(zp[1], pack2(a.z, a.w)); d = fma2(s, s, d);
            s = add2(zp[2], pack2(c.x, c.y)); d = fma2(s, s, d);
            s = add2(zp[3], pack2(c.z, c.w)); d = fma2(s, s, d);
            float dx, dy; unpack2(d, dx, dy);
            const float dist = dx + dy;
            const float bo = best1;
            best1 = fminf(bo, dist);
            bi1   = (dist < bo) ? (kk + 32) : bi1;
        }
    }

    // Merge: strict < keeps tracker 0 (lower k) on ties -> matches argmin.
    const int kb = (best1 < best0) ? bi1 : bi0;

    if (qout) {
        const float4 q0 = cb[2 * kb];
        const float4 q1 = cb[2 * kb + 1];
        float* qb = qout + ((b * Cn + l * CDn) * Hn + h) * Wn + w;
        qb[0 * Hn * Wn] = -q0.x;
        qb[1 * Hn * Wn] = -q0.y;
        qb[2 * Hn * Wn] = -q0.z;
        qb[3 * Hn * Wn] = -q0.w;
        qb[4 * Hn * Wn] = -q1.x;
        qb[5 * Hn * Wn] = -q1.y;
        qb[6 * Hn * Wn] = -q1.z;
        qb[7 * Hn * Wn] = -q1.w;
    }
    const long long io = (((long long)b * Hn + h) * Wn + w) * Ln + l;
    if (idxf) idxf[io] = (float)kb;
    if (idxi) idxi[io] = kb;
}

extern "C" void kernel_launch(void* const* d_in, const int* in_sizes, int n_in,
                              void* d_out, int out_size)
{
    const float* z     = (const float*)d_in[0];
    const float* codes = (const float*)d_in[1];
    // Defensive: if input order is (codes, z), swap by element count.
    if (n_in >= 2 && in_sizes[0] == Ln * Kn * CDn && in_sizes[1] == Bn * Cn * Hn * Wn) {
        codes = (const float*)d_in[0];
        z     = (const float*)d_in[1];
    }

    const int NQ = Bn * Cn * Hn * Wn;  // 2097152
    const int NI = Bn * Hn * Wn * Ln;  // 262144

    float* qout = nullptr;
    float* idxf = nullptr;
    int*   idxi = nullptr;

    if (out_size >= NQ + NI) {           // both outputs, flattened, float dtype
        qout = (float*)d_out;
        idxf = (float*)d_out + NQ;
    } else if (out_size == NI) {         // idx only -> int dtype
        idxi = (int*)d_out;
    } else {                             // quantized only
        qout = (float*)d_out;
    }

    dim3 grid(Ln / 2, Hn, Bn);       // (8, 64, 4) = 2048 blocks
    dim3 block(64, 2, 1);            // 128 threads
    vq_kernel<<<grid, block>>>(z, codes, qout, idxf, idxi);
}

// round 6
// speedup vs baseline: 1.1233x; 1.1233x over previous
#include <cuda_runtime.h>

// Problem constants (fixed shapes from reference)
#define Bn  4
#define Cn  128
#define Hn  64
#define Wn  64
#define Ln  16
#define Kn  64
#define CDn 8

typedef unsigned long long u64;

// ---- packed f32x2 helpers (sm_100+ PTX; ptxas won't auto-fuse these) ----
__device__ __forceinline__ u64 pack2(float x, float y) {
    u64 r; asm("mov.b64 %0, {%1, %2};" : "=l"(r) : "f"(x), "f"(y)); return r;
}
__device__ __forceinline__ void unpack2(u64 v, float& x, float& y) {
    asm("mov.b64 {%0, %1}, %2;" : "=f"(x), "=f"(y) : "l"(v));
}
__device__ __forceinline__ u64 add2(u64 a, u64 b) {
    u64 d; asm("add.rn.f32x2 %0, %1, %2;" : "=l"(d) : "l"(a), "l"(b)); return d;
}
__device__ __forceinline__ u64 fma2(u64 a, u64 b, u64 c) {
    u64 d; asm("fma.rn.f32x2 %0, %1, %2, %3;" : "=l"(d) : "l"(a), "l"(b), "l"(c)); return d;
}
__device__ __forceinline__ u64 mul2(u64 a, u64 b) {
    u64 d; asm("mul.rn.f32x2 %0, %1, %2;" : "=l"(d) : "l"(a), "l"(b)); return d;
}

// One thread: one (b, l, w) slot at TWO pixels (h0, h0+1); code LDS.128s are
// shared across both pixels; each warp has a single l -> all code smem reads
// are broadcasts.
//
// KEY CHANGES vs best-so-far (R4):
//  * #pragma unroll 8 -> loop body ~3.4 KB fits the 6 KB L0 I$ (the fully
//    unrolled 27 KB body was thrashing instruction fetch -> issue pinned 50%)
//  * __launch_bounds__(128, 9) -> ~56 regs, 9 blocks = 36 warps/SM, 1 wave.
//
// Argmin: two independent trackers per pixel (k in [0,32) and [32,64)).
//   best = fminf(best, dist)           -> FMNMX, 4-cyc loop chain
//   bi   = (dist < best_old) ? k : bi  -> SEL hangs off the chain
// Identical semantics to sequential strict-< argmin (first k wins ties).
__global__ __launch_bounds__(128, 9) void vq_kernel(
    const float* __restrict__ z,      // (B, C, H, W)
    const float* __restrict__ codes,  // (L, K, CD)
    float* __restrict__ qout,         // (B, C, H, W) or null
    float* __restrict__ idxf,         // (B, H, W, L) as float or null
    int*   __restrict__ idxi)         // (B, H, W, L) as int or null
{
    // Negated codes for this block's 2 l-slots: (z + (-c)) == (z - c) exactly.
    __shared__ __align__(16) float cneg[2 * Kn * CDn];  // 4 KB

    const int tid = threadIdx.y * 64 + threadIdx.x;
    const int l0  = blockIdx.x * 2;

    #pragma unroll
    for (int i = tid; i < 2 * Kn * CDn / 4; i += 128) {
        const float4 v = reinterpret_cast<const float4*>(codes + l0 * Kn * CDn)[i];
        reinterpret_cast<float4*>(cneg)[i] = make_float4(-v.x, -v.y, -v.z, -v.w);
    }
    __syncthreads();

    const int w  = threadIdx.x;
    const int ls = threadIdx.y;
    const int l  = l0 + ls;
    const int h0 = blockIdx.y * 2;
    const int b  = blockIdx.z;

    // Load z for 2 pixels x 8 channels (channel stride = H*W, coalesced over w)
    u64 zp[2][4];
    #pragma unroll
    for (int i = 0; i < 4; i++) {
        const float* p =
            z + (((b * Cn + l * CDn + 2 * i) * Hn + h0) * Wn + w);
        const float a0 = p[0];
        const float a1 = p[Wn];
        const float b0 = p[Hn * Wn];
        const float b1 = p[Hn * Wn + Wn];
        zp[0][i] = pack2(a0, b0);
        zp[1][i] = pack2(a1, b1);
    }

    // Codes for this l as float4 pairs: code k -> cb[2k], cb[2k+1]
    const float4* __restrict__ cb =
        reinterpret_cast<const float4*>(cneg + ls * Kn * CDn);

    float best[2][2] = {{3.4e38f, 3.4e38f}, {3.4e38f, 3.4e38f}};
    int   bi[2][2]   = {{0, 32}, {0, 32}};

    #pragma unroll 8
    for (int kk = 0; kk < 32; kk++) {
        #pragma unroll
        for (int t = 0; t < 2; t++) {          // tracker: k = kk + 32*t
            const int k = kk + 32 * t;
            const float4 a = cb[2 * k];
            const float4 c = cb[2 * k + 1];
            const u64 c0 = pack2(a.x, a.y);
            const u64 c1 = pack2(a.z, a.w);
            const u64 c2 = pack2(c.x, c.y);
            const u64 c3 = pack2(c.z, c.w);
            #pragma unroll
            for (int p = 0; p < 2; p++) {      // pixel
                u64 d, s;
                s = add2(zp[p][0], c0); d = mul2(s, s);
                s = add2(zp[p][1], c1); d = fma2(s, s, d);
                s = add2(zp[p][2], c2); d = fma2(s, s, d);
                s = add2(zp[p][3], c3); d = fma2(s, s, d);
                float dx, dy; unpack2(d, dx, dy);
                const float dist = dx + dy;
                // FMNMX chain + pred-selected index (strict <, first wins)
                const float bo = best[p][t];
                best[p][t] = fminf(bo, dist);
                bi[p][t]   = (dist < bo) ? k : bi[p][t];
            }
        }
    }

    #pragma unroll
    for (int p = 0; p < 2; p++) {
        // Merge trackers: strict < keeps tracker 0 (lower k) on ties.
        const int kb = (best[p][1] < best[p][0]) ? bi[p][1] : bi[p][0];
        const int h  = h0 + p;
        if (qout) {
            const float4 q0 = cb[2 * kb];
            const float4 q1 = cb[2 * kb + 1];
            float* qb = qout + ((b * Cn + l * CDn) * Hn + h) * Wn + w;
            qb[0 * Hn * Wn] = -q0.x;
            qb[1 * Hn * Wn] = -q0.y;
            qb[2 * Hn * Wn] = -q0.z;
            qb[3 * Hn * Wn] = -q0.w;
            qb[4 * Hn * Wn] = -q1.x;
            qb[5 * Hn * Wn] = -q1.y;
            qb[6 * Hn * Wn] = -q1.z;
            qb[7 * Hn * Wn] = -q1.w;
        }
        const long long io = (((long long)b * Hn + h) * Wn + w) * Ln + l;
        if (idxf) idxf[io] = (float)kb;
        if (idxi) idxi[io] = kb;
    }
}

extern "C" void kernel_launch(void* const* d_in, const int* in_sizes, int n_in,
                              void* d_out, int out_size)
{
    const float* z     = (const float*)d_in[0];
    const float* codes = (const float*)d_in[1];
    // Defensive: if input order is (codes, z), swap by element count.
    if (n_in >= 2 && in_sizes[0] == Ln * Kn * CDn && in_sizes[1] == Bn * Cn * Hn * Wn) {
        codes = (const float*)d_in[0];
        z     = (const float*)d_in[1];
    }

    const int NQ = Bn * Cn * Hn * Wn;  // 2097152
    const int NI = Bn * Hn * Wn * Ln;  // 262144

    float* qout = nullptr;
    float* idxf = nullptr;
    int*   idxi = nullptr;

    if (out_size >= NQ + NI) {           // both outputs, flattened, float dtype
        qout = (float*)d_out;
        idxf = (float*)d_out + NQ;
    } else if (out_size == NI) {         // idx only -> int dtype
        idxi = (int*)d_out;
    } else {                             // quantized only
        qout = (float*)d_out;
    }

    dim3 grid(Ln / 2, Hn / 2, Bn);   // (8, 32, 4) = 1024 blocks
    dim3 block(64, 2, 1);            // 128 threads
    vq_kernel<<<grid, block>>>(z, codes, qout, idxf, idxi);
}